// round 16
// baseline (speedup 1.0000x reference)
#include <cuda_runtime.h>
#include <cuda_fp16.h>
#include <math.h>
#include <stdint.h>

#define NN   24576
#define DIN  92
#define DINP 96
#define DM   512
#define NH   8
#define HD   64
#define NL   3
#define DFF  2048
#define BG   128
#define LN_EPS 1e-5f

// ---------------- scratch (static device globals; no allocs allowed) --------
__device__ float g_h[(size_t)NN * DM];          // f32 hidden (residual/pool)
__device__ float g_qkv[(size_t)NN * 3 * DM];    // f32 ffn2-out scratch
__device__ float g_x[(size_t)NN * DM];          // f32 post-LN1
__device__ float g_pooled[BG * DM];
__device__ int   g_counts[BG];
__device__ int   g_starts[BG];

__device__ __half g_h16[(size_t)NN * DM];       // f16 of hidden
__device__ __half g_x16[(size_t)NN * DM];       // f16 of post-LN1
__device__ __half g_t16[(size_t)NN * DM];       // f16 attn out
__device__ __half g_f16[(size_t)NN * DFF];      // f16 ffn hidden
__device__ __half g_qkv16[(size_t)NN * 3 * DM]; // f16 qkv
__device__ __half g_nf16[(size_t)NN * DINP];    // f16 node features (padded)
__device__ __half g_w16[9486336];               // f16 weights (all layers + emb)

// f32 buffer ids
#define BUF_H    0
#define BUF_QKV  1
#define BUF_X    2
__device__ __forceinline__ float* buf_ptr(int id) {
    switch (id) {
        case BUF_H:   return g_h;
        case BUF_QKV: return g_qkv;
        default:      return g_x;
    }
}
// f16 buffer ids
#define F16_H    0
#define F16_X    1
#define F16_T    2
#define F16_F    3
#define F16_QKV  4
#define F16_NF   5
__device__ __forceinline__ __half* f16_ptr(int id) {
    switch (id) {
        case F16_H: return g_h16;
        case F16_X: return g_x16;
        case F16_T: return g_t16;
        case F16_F: return g_f16;
        case F16_QKV: return g_qkv16;
        default:    return g_nf16;
    }
}

// weight offsets in g_w16 (halves)
#define IPW_OFF 0
#define IPW_PER (3 * DM * DM)
#define OW_OFF  (3 * IPW_PER)
#define OW_PER  (DM * DM)
#define F1W_OFF (OW_OFF + 3 * OW_PER)
#define F1W_PER (DFF * DM)
#define F2W_OFF (F1W_OFF + 3 * F1W_PER)
#define F2W_PER (DM * DFF)
#define EMBW_OFF (F2W_OFF + 3 * F2W_PER)        // 9437184; 512*96 = 49152

// ---------------- PTX helpers ------------------------------------------------
__device__ __forceinline__ uint32_t smem_u32(const void* p) {
    uint32_t a;
    asm("{ .reg .u64 t; cvta.to.shared.u64 t, %1; cvt.u32.u64 %0, t; }"
        : "=r"(a) : "l"(p));
    return a;
}
#define CPA16(dst, src) \
    asm volatile("cp.async.ca.shared.global [%0], [%1], 16;" :: "r"(dst), "l"(src))
#define CPCOMMIT() asm volatile("cp.async.commit_group;" ::: "memory")
#define CPWAIT1()  asm volatile("cp.async.wait_group 1;" ::: "memory")
#define CPWAIT0()  asm volatile("cp.async.wait_group 0;" ::: "memory")
#define LDMX4(r0, r1, r2, r3, a) \
    asm volatile("ldmatrix.sync.aligned.m8n8.x4.shared.b16 {%0,%1,%2,%3}, [%4];" \
                 : "=r"(r0), "=r"(r1), "=r"(r2), "=r"(r3) : "r"(a))

__device__ __forceinline__ void mma_f16(float* c, const uint32_t* a,
                                        uint32_t b0, uint32_t b1) {
    asm volatile(
        "mma.sync.aligned.m16n8k16.row.col.f32.f16.f16.f32 "
        "{%0,%1,%2,%3}, {%4,%5,%6,%7}, {%8,%9}, {%0,%1,%2,%3};"
        : "+f"(c[0]), "+f"(c[1]), "+f"(c[2]), "+f"(c[3])
        : "r"(a[0]), "r"(a[1]), "r"(a[2]), "r"(a[3]), "r"(b0), "r"(b1));
}
__device__ __forceinline__ uint32_t pack_f16x2(float even, float odd) {
    uint32_t r;
    asm("cvt.rn.f16x2.f32 %0, %1, %2;" : "=r"(r) : "f"(odd), "f"(even));
    return r;
}

// ---------------- graph bookkeeping -----------------------------------------
__global__ __launch_bounds__(256) void k_bookkeep(const int* __restrict__ b32)
{
    __shared__ int s_cnt[BG];
    __shared__ int s_any;
    int tid = threadIdx.x;

    if (tid == 0) s_any = 0;
    for (int i = tid; i < BG; i += 256) s_cnt[i] = 0;
    __syncthreads();

    int any = 0;
    for (int i = (NN / 2) + 1 + 2 * tid; i < NN; i += 2 * 256)
        if (b32[i] != 0) any = 1;
    if (any) atomicOr(&s_any, 1);
    __syncthreads();
    int is64 = (s_any == 0);

    for (int i = tid; i < NN; i += 256) {
        int v = is64 ? b32[2 * i] : b32[i];
        v = min(max(v, 0), BG - 1);
        atomicAdd(&s_cnt[v], 1);
    }
    __syncthreads();

    if (tid == 0) {
        int s = 0;
        for (int i = 0; i < BG; i++) {
            g_counts[i] = s_cnt[i];
            g_starts[i] = s;
            s += s_cnt[i];
        }
    }
}

// ---------------- weight + input conversion fp32 -> fp16 ---------------------
__device__ __forceinline__ void conv_region(
    const float* __restrict__ src, __half* __restrict__ dst, size_t n,
    size_t gid, size_t stride)
{
    __half2* d2 = (__half2*)dst;
    const float2* s2 = (const float2*)src;
    for (size_t i = gid; i < n / 2; i += stride)
        d2[i] = __floats2half2_rn(s2[i].x, s2[i].y);
}

__global__ __launch_bounds__(256) void k_wconvert(
    const float* __restrict__ ipw, const float* __restrict__ ow,
    const float* __restrict__ f1w, const float* __restrict__ f2w,
    const float* __restrict__ nf, const float* __restrict__ embw)
{
    size_t gid = (size_t)blockIdx.x * 256 + threadIdx.x;
    size_t stride = (size_t)gridDim.x * 256;
    conv_region(ipw, g_w16 + IPW_OFF, 3 * (size_t)IPW_PER, gid, stride);
    conv_region(ow,  g_w16 + OW_OFF,  3 * (size_t)OW_PER,  gid, stride);
    conv_region(f1w, g_w16 + F1W_OFF, 3 * (size_t)F1W_PER, gid, stride);
    conv_region(f2w, g_w16 + F2W_OFF, 3 * (size_t)F2W_PER, gid, stride);
    // node features: pad 92 -> 96
    for (size_t i = gid; i < (size_t)NN * DINP; i += stride) {
        int row = (int)(i / DINP), col = (int)(i % DINP);
        g_nf16[i] = __float2half((col < DIN) ? nf[(size_t)row * DIN + col] : 0.f);
    }
    // emb weights: pad 92 -> 96
    for (size_t i = gid; i < (size_t)DM * DINP; i += stride) {
        int row = (int)(i / DINP), col = (int)(i % DINP);
        g_w16[EMBW_OFF + i] =
            __float2half((col < DIN) ? embw[(size_t)row * DIN + col] : 0.f);
    }
}

// ---------------- fp16 tensor GEMM: C = A[M,K] @ W[N,K]^T + bias ------------
// 128x128 CTA tile, 128 threads (4 warps as 2Mx2N), warp tile 64x64,
// BK=32, 3-stage cp.async pipeline. 2 CTAs/SM resident.
#define LDW 20                       // words per smem row (32 halves + pad)
#define STG_B (128 * LDW * 4)        // one operand stage = 10240 bytes
#define NSTAGE 3
#define GEMM_SMEM (NSTAGE * 2 * STG_B)   // 61440

__global__ void __launch_bounds__(128, 2) gemm_tc(
    int aid, int woff, const float* __restrict__ bias,
    int cid, int out16, int act, int M, int K, int Nout)
{
    extern __shared__ uint32_t dsm[];
    const __half* A = f16_ptr(aid);
    const __half* W = g_w16 + woff;

    const int tid  = threadIdx.x;
    const int warp = tid >> 5;
    const int lane = tid & 31;
    const int g    = lane >> 2;
    const int tig  = lane & 3;
    const int wm   = (warp >> 1) * 64;   // 2 warps in M
    const int wn   = (warp & 1) * 64;    // 2 warps in N
    const int m0 = blockIdx.y * 128;
    const int n0 = blockIdx.x * 128;

    const uint32_t sbase = smem_u32(dsm);

    // loader: thread -> row tid (0..127), 4 chunks of 16B covering 32 halves
    const __half* Aga = A + (size_t)(m0 + tid) * K;
    const __half* Wga = W + (size_t)(n0 + tid) * K;
    const uint32_t sRow = tid * LDW * 4;

    // ldmatrix per-lane offsets
    const int grp = lane >> 3, l8 = lane & 7;
    const int rsel = (grp & 1) * 8;
    const int kselB = (grp >> 1) * 16;
    uint32_t aoff[4], boff[4];
    #pragma unroll
    for (int mb = 0; mb < 4; mb++)
        aoff[mb] = (wm + mb * 16 + rsel + l8) * 80 + kselB;
    #pragma unroll
    for (int nb = 0; nb < 4; nb++)
        boff[nb] = (wn + nb * 16 + rsel + l8) * 80 + kselB;

    float acc[4][8][4];
    #pragma unroll
    for (int i = 0; i < 4; i++)
        #pragma unroll
        for (int j = 0; j < 8; j++)
            #pragma unroll
            for (int r = 0; r < 4; r++) acc[i][j][r] = 0.f;

    const int S = K >> 5;

#define ISSUE(k0, st)                                               \
    do {                                                            \
        uint32_t ab = sbase + (st) * STG_B;                         \
        uint32_t wb = sbase + NSTAGE * STG_B + (st) * STG_B;        \
        CPA16(ab + sRow,      Aga + (k0));                          \
        CPA16(ab + sRow + 16, Aga + (k0) + 8);                      \
        CPA16(ab + sRow + 32, Aga + (k0) + 16);                     \
        CPA16(ab + sRow + 48, Aga + (k0) + 24);                     \
        CPA16(wb + sRow,      Wga + (k0));                          \
        CPA16(wb + sRow + 16, Wga + (k0) + 8);                      \
        CPA16(wb + sRow + 32, Wga + (k0) + 16);                     \
        CPA16(wb + sRow + 48, Wga + (k0) + 24);                     \
        CPCOMMIT();                                                 \
    } while (0)

#define COMPUTE(st)                                                          \
    do {                                                                     \
        uint32_t ab = sbase + (st) * STG_B;                                  \
        uint32_t wb = sbase + NSTAGE * STG_B + (st) * STG_B;                 \
        _Pragma("unroll")                                                    \
        for (int ks = 0; ks < 2; ks++) {                                     \
            uint32_t kB = ks * 32;                                           \
            uint32_t af[4][4];                                               \
            _Pragma("unroll")                                                \
            for (int mb = 0; mb < 4; mb++)                                   \
                LDMX4(af[mb][0], af[mb][1], af[mb][2], af[mb][3],            \
                      ab + aoff[mb] + kB);                                   \
            _Pragma("unroll")                                                \
            for (int nb = 0; nb < 4; nb++) {                                 \
                uint32_t b0, b1, b2, b3;                                     \
                LDMX4(b0, b1, b2, b3, wb + boff[nb] + kB);                   \
                _Pragma("unroll")                                            \
                for (int mb = 0; mb < 4; mb++) {                             \
                    mma_f16(acc[mb][2 * nb],     af[mb], b0, b2);            \
                    mma_f16(acc[mb][2 * nb + 1], af[mb], b1, b3);            \
                }                                                            \
            }                                                                \
        }                                                                    \
    } while (0)

    ISSUE(0, 0);
    ISSUE(32, 1);
    for (int s = 0; s < S; s++) {
        if (s == S - 1) CPWAIT0(); else CPWAIT1();
        __syncthreads();
        if (s + 2 < S) ISSUE((s + 2) * 32, (s + 2) % NSTAGE);
        COMPUTE(s % NSTAGE);
    }
#undef ISSUE
#undef COMPUTE

    // epilogue
    if (out16 == 1) {
        __half* C = f16_ptr(cid);
        #pragma unroll
        for (int j = 0; j < 8; j++) {
            int col = n0 + wn + j * 8 + 2 * tig;
            float2 bv = *(const float2*)(bias + col);
            #pragma unroll
            for (int mb = 0; mb < 4; mb++) {
                int row0 = m0 + wm + mb * 16 + g;
                float v0 = acc[mb][j][0] + bv.x;
                float v1 = acc[mb][j][1] + bv.y;
                float v2 = acc[mb][j][2] + bv.x;
                float v3 = acc[mb][j][3] + bv.y;
                if (act) {
                    v0 = fmaxf(v0, 0.f); v1 = fmaxf(v1, 0.f);
                    v2 = fmaxf(v2, 0.f); v3 = fmaxf(v3, 0.f);
                }
                *(uint32_t*)(C + (size_t)row0 * Nout + col)       = pack_f16x2(v0, v1);
                *(uint32_t*)(C + (size_t)(row0 + 8) * Nout + col) = pack_f16x2(v2, v3);
            }
        }
    } else if (out16 == 0) {
        float* C = buf_ptr(cid);
        #pragma unroll
        for (int j = 0; j < 8; j++) {
            int col = n0 + wn + j * 8 + 2 * tig;
            float2 bv = *(const float2*)(bias + col);
            #pragma unroll
            for (int mb = 0; mb < 4; mb++) {
                int row0 = m0 + wm + mb * 16 + g;
                float v0 = acc[mb][j][0] + bv.x;
                float v1 = acc[mb][j][1] + bv.y;
                float v2 = acc[mb][j][2] + bv.x;
                float v3 = acc[mb][j][3] + bv.y;
                if (act) {
                    v0 = fmaxf(v0, 0.f); v1 = fmaxf(v1, 0.f);
                    v2 = fmaxf(v2, 0.f); v3 = fmaxf(v3, 0.f);
                }
                *(float2*)(C + (size_t)row0 * Nout + col)       = make_float2(v0, v1);
                *(float2*)(C + (size_t)(row0 + 8) * Nout + col) = make_float2(v2, v3);
            }
        }
    } else {   // out16 == 2: embedding -> g_h (f32) + g_h16 (f16)
        #pragma unroll
        for (int j = 0; j < 8; j++) {
            int col = n0 + wn + j * 8 + 2 * tig;
            float2 bv = *(const float2*)(bias + col);
            #pragma unroll
            for (int mb = 0; mb < 4; mb++) {
                int row0 = m0 + wm + mb * 16 + g;
                float v0 = acc[mb][j][0] + bv.x;
                float v1 = acc[mb][j][1] + bv.y;
                float v2 = acc[mb][j][2] + bv.x;
                float v3 = acc[mb][j][3] + bv.y;
                *(float2*)(g_h + (size_t)row0 * Nout + col)       = make_float2(v0, v1);
                *(float2*)(g_h + (size_t)(row0 + 8) * Nout + col) = make_float2(v2, v3);
                *(uint32_t*)(g_h16 + (size_t)row0 * Nout + col)       = pack_f16x2(v0, v1);
                *(uint32_t*)(g_h16 + (size_t)(row0 + 8) * Nout + col) = pack_f16x2(v2, v3);
            }
        }
    }
}

// ---------------- tensor-core ragged flash attention -------------------------
// 128 threads (4 warps), grid (BG, NH, 16 q-tiles of 32).
__global__ __launch_bounds__(128) void attn_kernel()
{
    int b  = blockIdx.x;
    int h  = blockIdx.y;
    int qt = blockIdx.z;
    int cnt = g_counts[b];
    int q0  = qt * 32;
    if (q0 >= cnt) return;
    int start = g_starts[b];
    int nq = min(32, cnt - q0);

    __shared__ __half Qs[32][72];
    __shared__ __half Ks[32][72];
    __shared__ __half Vs[64][40];
    __shared__ __half Ps[32][40];
    __shared__ float  Sc[32][34];
    __shared__ float  s_m[32], s_l[32], s_corr[32];

    const int tid  = threadIdx.x;
    const int warp = tid >> 5;
    const int lane = tid & 31;
    const int grp = lane >> 3, l8 = lane & 7;
    const int rsel = (grp & 1) * 8;
    const int ksel16 = (grp >> 1) * 16;
    const int qr = lane >> 2;
    const int qc = lane & 3;

    const uint32_t qb = smem_u32(&Qs[0][0]);
    const uint32_t kb = smem_u32(&Ks[0][0]);
    const uint32_t vb = smem_u32(&Vs[0][0]);
    const uint32_t pb = smem_u32(&Ps[0][0]);

    {
        const __half* Qg = g_qkv16 + (size_t)(start + q0) * (3 * DM) + h * HD;
        #pragma unroll
        for (int c = tid; c < 256; c += 128) {
            int r = c >> 3, off = (c & 7) * 8;
            uint4 v = make_uint4(0, 0, 0, 0);
            if (r < nq) v = *(const uint4*)(Qg + (size_t)r * (3 * DM) + off);
            *(uint4*)(&Qs[r][off]) = v;
        }
    }
    if (tid < 32) { s_m[tid] = -INFINITY; s_l[tid] = 0.f; }

    float accO[2][2][4];
    #pragma unroll
    for (int i = 0; i < 2; i++)
        #pragma unroll
        for (int j = 0; j < 2; j++)
            #pragma unroll
            for (int r = 0; r < 4; r++) accO[i][j][r] = 0.f;

    const int mi = warp >> 1;
    const int nj = warp & 1;
    const float scale = 0.125f;

    int ktiles = (cnt + 31) >> 5;
    for (int kt = 0; kt < ktiles; kt++) {
        int k0 = kt * 32;
        int nk = min(32, cnt - k0);
        __syncthreads();

        const __half* Kg = g_qkv16 + (size_t)(start + k0) * (3 * DM) + DM + h * HD;
        #pragma unroll
        for (int c = tid; c < 256; c += 128) {
            int r = c >> 3, off = (c & 7) * 8;
            if (r < nk)
                *(uint4*)(&Ks[r][off]) = *(const uint4*)(Kg + (size_t)r * (3 * DM) + off);
        }
        {
            const __half* Vg = g_qkv16 + (size_t)(start + k0) * (3 * DM) + 2 * DM + h * HD;
            int r = lane, dc = warp * 16;
            if (r < nk) {
                const __half* src = Vg + (size_t)r * (3 * DM) + dc;
                #pragma unroll
                for (int i = 0; i < 16; i++) Vs[dc + i][r] = src[i];
            } else {
                #pragma unroll
                for (int i = 0; i < 16; i++) Vs[dc + i][r] = __ushort_as_half(0);
            }
        }
        __syncthreads();

        float accS[2][4] = {{0.f, 0.f, 0.f, 0.f}, {0.f, 0.f, 0.f, 0.f}};
        #pragma unroll
        for (int kc = 0; kc < 4; kc++) {
            uint32_t a0, a1, a2, a3, b0, b1, b2, b3;
            LDMX4(a0, a1, a2, a3,
                  qb + (mi * 16 + rsel + l8) * 144 + kc * 32 + ksel16);
            LDMX4(b0, b1, b2, b3,
                  kb + (nj * 16 + rsel + l8) * 144 + kc * 32 + ksel16);
            uint32_t af[4] = {a0, a1, a2, a3};
            mma_f16(accS[0], af, b0, b2);
            mma_f16(accS[1], af, b1, b3);
        }
        {
            int r0 = mi * 16 + qr;
            #pragma unroll
            for (int jn = 0; jn < 2; jn++) {
                int c0 = nj * 16 + jn * 8 + 2 * qc;
                Sc[r0][c0]         = accS[jn][0] * scale;
                Sc[r0][c0 + 1]     = accS[jn][1] * scale;
                Sc[r0 + 8][c0]     = accS[jn][2] * scale;
                Sc[r0 + 8][c0 + 1] = accS[jn][3] * scale;
            }
        }
        __syncthreads();

        {
            int q = tid >> 2, s4 = tid & 3;
            float v[8];
            float mx = -INFINITY;
            #pragma unroll
            for (int i = 0; i < 8; i++) {
                int k = s4 * 8 + i;
                v[i] = (k < nk) ? Sc[q][k] : -INFINITY;
                mx = fmaxf(mx, v[i]);
            }
            mx = fmaxf(mx, __shfl_xor_sync(0xffffffffu, mx, 1));
            mx = fmaxf(mx, __shfl_xor_sync(0xffffffffu, mx, 2));
            float mold = s_m[q];
            float mnew = fmaxf(mold, mx);
            float sum = 0.f;
            float p[8];
            #pragma unroll
            for (int i = 0; i < 8; i++) {
                p[i] = __expf(v[i] - mnew);
                sum += p[i];
            }
            sum += __shfl_xor_sync(0xffffffffu, sum, 1);
            sum += __shfl_xor_sync(0xffffffffu, sum, 2);
            #pragma unroll
            for (int i = 0; i < 4; i++)
                *(uint32_t*)(&Ps[q][s4 * 8 + 2 * i]) = pack_f16x2(p[2 * i], p[2 * i + 1]);
            if (s4 == 0) {
                float corr = __expf(mold - mnew);
                s_m[q] = mnew;
                s_l[q] = s_l[q] * corr + sum;
                s_corr[q] = corr;
            }
        }
        __syncthreads();

        {
            #pragma unroll
            for (int m2 = 0; m2 < 2; m2++) {
                float c0 = s_corr[m2 * 16 + qr];
                float c1 = s_corr[m2 * 16 + qr + 8];
                #pragma unroll
                for (int jn = 0; jn < 2; jn++) {
                    accO[m2][jn][0] *= c0; accO[m2][jn][1] *= c0;
                    accO[m2][jn][2] *= c1; accO[m2][jn][3] *= c1;
                }
            }
            #pragma unroll
            for (int kc = 0; kc < 2; kc++) {
                uint32_t b0, b1, b2, b3;
                LDMX4(b0, b1, b2, b3,
                      vb + (warp * 16 + rsel + l8) * 80 + kc * 32 + ksel16);
                #pragma unroll
                for (int m2 = 0; m2 < 2; m2++) {
                    uint32_t a0, a1, a2, a3;
                    LDMX4(a0, a1, a2, a3,
                          pb + (m2 * 16 + rsel + l8) * 80 + kc * 32 + ksel16);
                    uint32_t af[4] = {a0, a1, a2, a3};
                    mma_f16(accO[m2][0], af, b0, b2);
                    mma_f16(accO[m2][1], af, b1, b3);
                }
            }
        }
    }

    #pragma unroll
    for (int m2 = 0; m2 < 2; m2++) {
        int r = m2 * 16 + qr;
        int r2 = r + 8;
        float inv  = (r  < nq) ? 1.f / s_l[r]  : 0.f;
        float inv2 = (r2 < nq) ? 1.f / s_l[r2] : 0.f;
        #pragma unroll
        for (int jn = 0; jn < 2; jn++) {
            int col = h * HD + warp * 16 + jn * 8 + 2 * qc;
            if (r < nq)
                *(uint32_t*)(g_t16 + (size_t)(start + q0 + r) * DM + col) =
                    pack_f16x2(accO[m2][jn][0] * inv, accO[m2][jn][1] * inv);
            if (r2 < nq)
                *(uint32_t*)(g_t16 + (size_t)(start + q0 + r2) * DM + col) =
                    pack_f16x2(accO[m2][jn][2] * inv2, accO[m2][jn][3] * inv2);
        }
    }
}

// ---------------- residual + layernorm (f32 out + f16 out) -------------------
__global__ __launch_bounds__(128) void ln_kernel(
    int rid, int did, int oid, int oid16,
    const float* __restrict__ gg, const float* __restrict__ bb)
{
    const float* resid = buf_ptr(rid);
    const float* delta = buf_ptr(did);
    float*       out   = buf_ptr(oid);
    __half*      out16 = f16_ptr(oid16);

    int row = blockIdx.x;
    int tid = threadIdx.x;
    size_t base = (size_t)row * DM;

    float v[4];
    float s = 0.f, sq = 0.f;
    #pragma unroll
    for (int i = 0; i < 4; i++) {
        int c = tid + i * 128;
        float x = resid[base + c] + delta[base + c];
        v[i] = x;
        s += x; sq += x * x;
    }
    __shared__ float shs[4], shq[4];
    #pragma unroll
    for (int o = 16; o > 0; o >>= 1) {
        s  += __shfl_down_sync(0xffffffffu, s, o);
        sq += __shfl_down_sync(0xffffffffu, sq, o);
    }
    int w = tid >> 5;
    if ((tid & 31) == 0) { shs[w] = s; shq[w] = sq; }
    __syncthreads();
    float ts = shs[0] + shs[1] + shs[2] + shs[3];
    float tq = shq[0] + shq[1] + shq[2] + shq[3];
    float mean = ts * (1.f / DM);
    float var  = tq * (1.f / DM) - mean * mean;
    float inv  = rsqrtf(fmaxf(var, 0.f) + LN_EPS);
    #pragma unroll
    for (int i = 0; i < 4; i++) {
        int c = tid + i * 128;
        float r = (v[i] - mean) * inv * gg[c] + bb[c];
        out[base + c] = r;
        out16[base + c] = __float2half(r);
    }
}

// ---------------- segment mean pool -----------------------------------------
__global__ __launch_bounds__(256) void pool_kernel()
{
    int b = blockIdx.x;
    int tid = threadIdx.x;
    int cnt = g_counts[b], st = g_starts[b];
    float a0 = 0.f, a1 = 0.f;
    for (int r = 0; r < cnt; r++) {
        size_t base = (size_t)(st + r) * DM;
        a0 += g_h[base + tid];
        a1 += g_h[base + tid + 256];
    }
    float inv = (cnt > 0) ? 1.f / (float)cnt : 0.f;
    g_pooled[b * DM + tid]       = a0 * inv;
    g_pooled[b * DM + tid + 256] = a1 * inv;
}

// ---------------- head ------------------------------------------------------
__global__ __launch_bounds__(256) void head_kernel(
    const float* __restrict__ w1, const float* __restrict__ b1,
    const float* __restrict__ w2, const float* __restrict__ b2,
    float* __restrict__ out)
{
    int b = blockIdx.x;
    int tid = threadIdx.x;
    __shared__ float ps[DM];
    ps[tid]       = g_pooled[b * DM + tid];
    ps[tid + 256] = g_pooled[b * DM + tid + 256];
    __syncthreads();

    int warp = tid >> 5, lane = tid & 31;
    float partial = 0.f;
    for (int j = warp; j < DM; j += 8) {
        float a = 0.f;
        const float* wr = w1 + (size_t)j * DM;
        for (int k = lane; k < DM; k += 32) a = fmaf(ps[k], wr[k], a);
        #pragma unroll
        for (int o = 16; o > 0; o >>= 1) a += __shfl_down_sync(0xffffffffu, a, o);
        if (lane == 0) {
            a += b1[j];
            float sil = a / (1.f + __expf(-a));
            partial = fmaf(sil, w2[j], partial);
        }
    }
    __shared__ float red[8];
    if (lane == 0) red[warp] = partial;
    __syncthreads();
    if (tid == 0) {
        float t = 0.f;
        #pragma unroll
        for (int i = 0; i < 8; i++) t += red[i];
        out[b] = t + b2[0];
    }
}

// ---------------- launch -----------------------------------------------------
extern "C" void kernel_launch(void* const* d_in, const int* in_sizes, int n_in,
                              void* d_out, int out_size)
{
    const float* node_features = (const float*)d_in[0];
    const int*   batch32       = (const int*)d_in[3];
    const float* emb_w    = (const float*)d_in[4];
    const float* emb_b    = (const float*)d_in[5];
    const float* in_proj_w = (const float*)d_in[6];
    const float* in_proj_b = (const float*)d_in[7];
    const float* out_w    = (const float*)d_in[8];
    const float* out_b    = (const float*)d_in[9];
    const float* ln1_g    = (const float*)d_in[10];
    const float* ln1_b    = (const float*)d_in[11];
    const float* ffn_w1   = (const float*)d_in[12];
    const float* ffn_b1   = (const float*)d_in[13];
    const float* ffn_w2   = (const float*)d_in[14];
    const float* ffn_b2   = (const float*)d_in[15];
    const float* ln2_g    = (const float*)d_in[16];
    const float* ln2_b    = (const float*)d_in[17];
    const float* head_w1  = (const float*)d_in[18];
    const float* head_b1  = (const float*)d_in[19];
    const float* head_w2  = (const float*)d_in[20];
    const float* head_b2  = (const float*)d_in[21];
    float* out = (float*)d_out;

    cudaFuncSetAttribute(gemm_tc, cudaFuncAttributeMaxDynamicSharedMemorySize,
                         GEMM_SMEM);

    k_bookkeep<<<1, 256>>>(batch32);
    k_wconvert<<<2048, 256>>>(in_proj_w, out_w, ffn_w1, ffn_w2,
                              node_features, emb_w);

    // embedding: nf16 @ embw^T (K=96 padded) -> g_h + g_h16
    gemm_tc<<<dim3(DM / 128, NN / 128), 128, GEMM_SMEM>>>(
        F16_NF, EMBW_OFF, emb_b, BUF_H, 2, 0, NN, DINP, DM);

    for (int l = 0; l < NL; l++) {
        const float* ipb = in_proj_b + (size_t)l * 3 * DM;
        const float* ob  = out_b + (size_t)l * DM;
        const float* f1b = ffn_b1 + (size_t)l * DFF;
        const float* f2b = ffn_b2 + (size_t)l * DM;

        // qkv = h16 @ ipw^T -> g_qkv16 (f16)
        gemm_tc<<<dim3(3 * DM / 128, NN / 128), 128, GEMM_SMEM>>>(
            F16_H, IPW_OFF + l * IPW_PER, ipb, F16_QKV, 1, 0, NN, DM, 3 * DM);

        // tensor-core attention -> g_t16
        attn_kernel<<<dim3(BG, NH, 16), 128>>>();

        // o proj = t16 @ ow^T -> g_x (f32)
        gemm_tc<<<dim3(DM / 128, NN / 128), 128, GEMM_SMEM>>>(
            F16_T, OW_OFF + l * OW_PER, ob, BUF_X, 0, 0, NN, DM, DM);

        // x = LN(h + o) -> g_x (f32) + g_x16
        ln_kernel<<<NN, 128>>>(BUF_H, BUF_X, BUF_X, F16_X,
                               ln1_g + (size_t)l * DM, ln1_b + (size_t)l * DM);

        // ffn1 = relu(x16 @ f1w^T) -> g_f16 (f16)
        gemm_tc<<<dim3(DFF / 128, NN / 128), 128, GEMM_SMEM>>>(
            F16_X, F1W_OFF + l * F1W_PER, f1b, F16_F, 1, 1, NN, DM, DFF);

        // ffn2 = f16 @ f2w^T -> g_qkv (f32 scratch)
        gemm_tc<<<dim3(DM / 128, NN / 128), 128, GEMM_SMEM>>>(
            F16_F, F2W_OFF + l * F2W_PER, f2b, BUF_QKV, 0, 0, NN, DFF, DM);

        // h = LN(x + ffn2) -> g_h (f32) + g_h16
        ln_kernel<<<NN, 128>>>(BUF_X, BUF_QKV, BUF_H, F16_H,
                               ln2_g + (size_t)l * DM, ln2_b + (size_t)l * DM);
    }

    pool_kernel<<<BG, 256>>>();
    head_kernel<<<BG, 256>>>(head_w1, head_b1, head_w2, head_b2, out);
}

// round 17
// speedup vs baseline: 1.2163x; 1.2163x over previous
#include <cuda_runtime.h>
#include <cuda_fp16.h>
#include <math.h>
#include <stdint.h>

#define NN   24576
#define DIN  92
#define DINP 96
#define DM   512
#define NH   8
#define HD   64
#define NL   3
#define DFF  2048
#define BG   128
#define LN_EPS 1e-5f

// ---------------- scratch (static device globals; no allocs allowed) --------
__device__ float g_h[(size_t)NN * DM];          // f32 hidden (residual/pool)
__device__ float g_qkv[(size_t)NN * 3 * DM];    // f32 ffn2-out scratch
__device__ float g_x[(size_t)NN * DM];          // f32 post-LN1
__device__ float g_pooled[BG * DM];
__device__ int   g_counts[BG];
__device__ int   g_starts[BG];

__device__ __half g_h16[(size_t)NN * DM];       // f16 of hidden
__device__ __half g_x16[(size_t)NN * DM];       // f16 of post-LN1
__device__ __half g_t16[(size_t)NN * DM];       // f16 attn out
__device__ __half g_f16[(size_t)NN * DFF];      // f16 ffn hidden
__device__ __half g_qkv16[(size_t)NN * 3 * DM]; // f16 qkv
__device__ __half g_nf16[(size_t)NN * DINP];    // f16 node features (padded)
__device__ __half g_w16[9486336];               // f16 weights (all layers + emb)

// f32 buffer ids
#define BUF_H    0
#define BUF_QKV  1
#define BUF_X    2
__device__ __forceinline__ float* buf_ptr(int id) {
    switch (id) {
        case BUF_H:   return g_h;
        case BUF_QKV: return g_qkv;
        default:      return g_x;
    }
}
// f16 buffer ids
#define F16_H    0
#define F16_X    1
#define F16_T    2
#define F16_F    3
#define F16_QKV  4
#define F16_NF   5
__device__ __forceinline__ __half* f16_ptr(int id) {
    switch (id) {
        case F16_H: return g_h16;
        case F16_X: return g_x16;
        case F16_T: return g_t16;
        case F16_F: return g_f16;
        case F16_QKV: return g_qkv16;
        default:    return g_nf16;
    }
}

// weight offsets in g_w16 (halves)
#define IPW_OFF 0
#define IPW_PER (3 * DM * DM)
#define OW_OFF  (3 * IPW_PER)
#define OW_PER  (DM * DM)
#define F1W_OFF (OW_OFF + 3 * OW_PER)
#define F1W_PER (DFF * DM)
#define F2W_OFF (F1W_OFF + 3 * F1W_PER)
#define F2W_PER (DM * DFF)
#define EMBW_OFF (F2W_OFF + 3 * F2W_PER)        // 9437184; 512*96 = 49152

// ---------------- PTX helpers ------------------------------------------------
__device__ __forceinline__ uint32_t smem_u32(const void* p) {
    uint32_t a;
    asm("{ .reg .u64 t; cvta.to.shared.u64 t, %1; cvt.u32.u64 %0, t; }"
        : "=r"(a) : "l"(p));
    return a;
}
#define CPA16(dst, src) \
    asm volatile("cp.async.ca.shared.global [%0], [%1], 16;" :: "r"(dst), "l"(src))
#define CPCOMMIT() asm volatile("cp.async.commit_group;" ::: "memory")
#define CPWAIT1()  asm volatile("cp.async.wait_group 1;" ::: "memory")
#define CPWAIT0()  asm volatile("cp.async.wait_group 0;" ::: "memory")
#define LDMX4(r0, r1, r2, r3, a) \
    asm volatile("ldmatrix.sync.aligned.m8n8.x4.shared.b16 {%0,%1,%2,%3}, [%4];" \
                 : "=r"(r0), "=r"(r1), "=r"(r2), "=r"(r3) : "r"(a))

__device__ __forceinline__ void mma_f16(float* c, const uint32_t* a,
                                        uint32_t b0, uint32_t b1) {
    asm volatile(
        "mma.sync.aligned.m16n8k16.row.col.f32.f16.f16.f32 "
        "{%0,%1,%2,%3}, {%4,%5,%6,%7}, {%8,%9}, {%0,%1,%2,%3};"
        : "+f"(c[0]), "+f"(c[1]), "+f"(c[2]), "+f"(c[3])
        : "r"(a[0]), "r"(a[1]), "r"(a[2]), "r"(a[3]), "r"(b0), "r"(b1));
}
__device__ __forceinline__ uint32_t pack_f16x2(float even, float odd) {
    uint32_t r;
    asm("cvt.rn.f16x2.f32 %0, %1, %2;" : "=r"(r) : "f"(odd), "f"(even));
    return r;
}

// ---------------- graph bookkeeping -----------------------------------------
__global__ __launch_bounds__(256) void k_bookkeep(const int* __restrict__ b32)
{
    __shared__ int s_cnt[BG];
    __shared__ int s_any;
    int tid = threadIdx.x;

    if (tid == 0) s_any = 0;
    for (int i = tid; i < BG; i += 256) s_cnt[i] = 0;
    __syncthreads();

    int any = 0;
    for (int i = (NN / 2) + 1 + 2 * tid; i < NN; i += 2 * 256)
        if (b32[i] != 0) any = 1;
    if (any) atomicOr(&s_any, 1);
    __syncthreads();
    int is64 = (s_any == 0);

    for (int i = tid; i < NN; i += 256) {
        int v = is64 ? b32[2 * i] : b32[i];
        v = min(max(v, 0), BG - 1);
        atomicAdd(&s_cnt[v], 1);
    }
    __syncthreads();

    if (tid == 0) {
        int s = 0;
        for (int i = 0; i < BG; i++) {
            g_counts[i] = s_cnt[i];
            g_starts[i] = s;
            s += s_cnt[i];
        }
    }
}

// ---------------- weight + input conversion fp32 -> fp16 ---------------------
__device__ __forceinline__ void conv_region(
    const float* __restrict__ src, __half* __restrict__ dst, size_t n,
    size_t gid, size_t stride)
{
    __half2* d2 = (__half2*)dst;
    const float2* s2 = (const float2*)src;
    for (size_t i = gid; i < n / 2; i += stride)
        d2[i] = __floats2half2_rn(s2[i].x, s2[i].y);
}

__global__ __launch_bounds__(256) void k_wconvert(
    const float* __restrict__ ipw, const float* __restrict__ ow,
    const float* __restrict__ f1w, const float* __restrict__ f2w,
    const float* __restrict__ nf, const float* __restrict__ embw)
{
    size_t gid = (size_t)blockIdx.x * 256 + threadIdx.x;
    size_t stride = (size_t)gridDim.x * 256;
    conv_region(ipw, g_w16 + IPW_OFF, 3 * (size_t)IPW_PER, gid, stride);
    conv_region(ow,  g_w16 + OW_OFF,  3 * (size_t)OW_PER,  gid, stride);
    conv_region(f1w, g_w16 + F1W_OFF, 3 * (size_t)F1W_PER, gid, stride);
    conv_region(f2w, g_w16 + F2W_OFF, 3 * (size_t)F2W_PER, gid, stride);
    // node features: pad 92 -> 96
    for (size_t i = gid; i < (size_t)NN * DINP; i += stride) {
        int row = (int)(i / DINP), col = (int)(i % DINP);
        g_nf16[i] = __float2half((col < DIN) ? nf[(size_t)row * DIN + col] : 0.f);
    }
    // emb weights: pad 92 -> 96
    for (size_t i = gid; i < (size_t)DM * DINP; i += stride) {
        int row = (int)(i / DINP), col = (int)(i % DINP);
        g_w16[EMBW_OFF + i] =
            __float2half((col < DIN) ? embw[(size_t)row * DIN + col] : 0.f);
    }
}

// ---------------- fp16 tensor GEMM: C = A[M,K] @ W[N,K]^T + bias ------------
// 128x128 CTA tile, 128 threads (4 warps as 2Mx2N), warp tile 64x64,
// BK=32, 3-stage cp.async pipeline, coalesced loader. 2 CTAs/SM resident.
#define LDW 20                       // words per smem row (32 halves + pad)
#define STG_B (128 * LDW * 4)        // one operand stage = 10240 bytes
#define NSTAGE 3
#define GEMM_SMEM (NSTAGE * 2 * STG_B)   // 61440

__global__ void __launch_bounds__(128, 2) gemm_tc(
    int aid, int woff, const float* __restrict__ bias,
    int cid, int out16, int act, int M, int K, int Nout)
{
    extern __shared__ uint32_t dsm[];
    const __half* A = f16_ptr(aid);
    const __half* W = g_w16 + woff;

    const int tid  = threadIdx.x;
    const int warp = tid >> 5;
    const int lane = tid & 31;
    const int g    = lane >> 2;
    const int tig  = lane & 3;
    const int wm   = (warp >> 1) * 64;   // 2 warps in M
    const int wn   = (warp & 1) * 64;    // 2 warps in N
    const int m0 = blockIdx.y * 128;
    const int n0 = blockIdx.x * 128;

    const uint32_t sbase = smem_u32(dsm);

    // coalesced loader: thread -> row (tid>>2) + 32*i, 16B chunk (tid&3)
    const int rowL = tid >> 2, chL = tid & 3;
    const __half* Aga = A + (size_t)(m0 + rowL) * K + chL * 8;
    const __half* Wga = W + (size_t)(n0 + rowL) * K + chL * 8;
    uint32_t sOff[4];
    #pragma unroll
    for (int i = 0; i < 4; i++)
        sOff[i] = ((rowL + 32 * i) * LDW + chL * 4) * 4;

    // ldmatrix per-lane offsets
    const int grp = lane >> 3, l8 = lane & 7;
    const int rsel = (grp & 1) * 8;
    const int kselB = (grp >> 1) * 16;
    uint32_t aoff[4], boff[4];
    #pragma unroll
    for (int mb = 0; mb < 4; mb++)
        aoff[mb] = (wm + mb * 16 + rsel + l8) * 80 + kselB;
    #pragma unroll
    for (int nb = 0; nb < 4; nb++)
        boff[nb] = (wn + nb * 16 + rsel + l8) * 80 + kselB;

    float acc[4][8][4];
    #pragma unroll
    for (int i = 0; i < 4; i++)
        #pragma unroll
        for (int j = 0; j < 8; j++)
            #pragma unroll
            for (int r = 0; r < 4; r++) acc[i][j][r] = 0.f;

    const int S = K >> 5;

#define ISSUE(k0, st)                                               \
    do {                                                            \
        uint32_t ab = sbase + (st) * STG_B;                         \
        uint32_t wb = sbase + NSTAGE * STG_B + (st) * STG_B;        \
        CPA16(ab + sOff[0], Aga + (k0));                            \
        CPA16(ab + sOff[1], Aga + (k0) + (size_t)32 * K);           \
        CPA16(ab + sOff[2], Aga + (k0) + (size_t)64 * K);           \
        CPA16(ab + sOff[3], Aga + (k0) + (size_t)96 * K);           \
        CPA16(wb + sOff[0], Wga + (k0));                            \
        CPA16(wb + sOff[1], Wga + (k0) + (size_t)32 * K);           \
        CPA16(wb + sOff[2], Wga + (k0) + (size_t)64 * K);           \
        CPA16(wb + sOff[3], Wga + (k0) + (size_t)96 * K);           \
        CPCOMMIT();                                                 \
    } while (0)

#define COMPUTE(st)                                                          \
    do {                                                                     \
        uint32_t ab = sbase + (st) * STG_B;                                  \
        uint32_t wb = sbase + NSTAGE * STG_B + (st) * STG_B;                 \
        _Pragma("unroll")                                                    \
        for (int ks = 0; ks < 2; ks++) {                                     \
            uint32_t kB = ks * 32;                                           \
            uint32_t af[4][4];                                               \
            _Pragma("unroll")                                                \
            for (int mb = 0; mb < 4; mb++)                                   \
                LDMX4(af[mb][0], af[mb][1], af[mb][2], af[mb][3],            \
                      ab + aoff[mb] + kB);                                   \
            _Pragma("unroll")                                                \
            for (int nb = 0; nb < 4; nb++) {                                 \
                uint32_t b0, b1, b2, b3;                                     \
                LDMX4(b0, b1, b2, b3, wb + boff[nb] + kB);                   \
                _Pragma("unroll")                                            \
                for (int mb = 0; mb < 4; mb++) {                             \
                    mma_f16(acc[mb][2 * nb],     af[mb], b0, b2);            \
                    mma_f16(acc[mb][2 * nb + 1], af[mb], b1, b3);            \
                }                                                            \
            }                                                                \
        }                                                                    \
    } while (0)

    ISSUE(0, 0);
    ISSUE(32, 1);
    for (int s = 0; s < S; s++) {
        if (s == S - 1) CPWAIT0(); else CPWAIT1();
        __syncthreads();
        if (s + 2 < S) ISSUE((s + 2) * 32, (s + 2) % NSTAGE);
        COMPUTE(s % NSTAGE);
    }
#undef ISSUE
#undef COMPUTE

    // epilogue
    if (out16 == 1) {
        __half* C = f16_ptr(cid);
        #pragma unroll
        for (int j = 0; j < 8; j++) {
            int col = n0 + wn + j * 8 + 2 * tig;
            float2 bv = *(const float2*)(bias + col);
            #pragma unroll
            for (int mb = 0; mb < 4; mb++) {
                int row0 = m0 + wm + mb * 16 + g;
                float v0 = acc[mb][j][0] + bv.x;
                float v1 = acc[mb][j][1] + bv.y;
                float v2 = acc[mb][j][2] + bv.x;
                float v3 = acc[mb][j][3] + bv.y;
                if (act) {
                    v0 = fmaxf(v0, 0.f); v1 = fmaxf(v1, 0.f);
                    v2 = fmaxf(v2, 0.f); v3 = fmaxf(v3, 0.f);
                }
                *(uint32_t*)(C + (size_t)row0 * Nout + col)       = pack_f16x2(v0, v1);
                *(uint32_t*)(C + (size_t)(row0 + 8) * Nout + col) = pack_f16x2(v2, v3);
            }
        }
    } else if (out16 == 0) {
        float* C = buf_ptr(cid);
        #pragma unroll
        for (int j = 0; j < 8; j++) {
            int col = n0 + wn + j * 8 + 2 * tig;
            float2 bv = *(const float2*)(bias + col);
            #pragma unroll
            for (int mb = 0; mb < 4; mb++) {
                int row0 = m0 + wm + mb * 16 + g;
                float v0 = acc[mb][j][0] + bv.x;
                float v1 = acc[mb][j][1] + bv.y;
                float v2 = acc[mb][j][2] + bv.x;
                float v3 = acc[mb][j][3] + bv.y;
                if (act) {
                    v0 = fmaxf(v0, 0.f); v1 = fmaxf(v1, 0.f);
                    v2 = fmaxf(v2, 0.f); v3 = fmaxf(v3, 0.f);
                }
                *(float2*)(C + (size_t)row0 * Nout + col)       = make_float2(v0, v1);
                *(float2*)(C + (size_t)(row0 + 8) * Nout + col) = make_float2(v2, v3);
            }
        }
    } else {   // out16 == 2: embedding -> g_h (f32) + g_h16 (f16)
        #pragma unroll
        for (int j = 0; j < 8; j++) {
            int col = n0 + wn + j * 8 + 2 * tig;
            float2 bv = *(const float2*)(bias + col);
            #pragma unroll
            for (int mb = 0; mb < 4; mb++) {
                int row0 = m0 + wm + mb * 16 + g;
                float v0 = acc[mb][j][0] + bv.x;
                float v1 = acc[mb][j][1] + bv.y;
                float v2 = acc[mb][j][2] + bv.x;
                float v3 = acc[mb][j][3] + bv.y;
                *(float2*)(g_h + (size_t)row0 * Nout + col)       = make_float2(v0, v1);
                *(float2*)(g_h + (size_t)(row0 + 8) * Nout + col) = make_float2(v2, v3);
                *(uint32_t*)(g_h16 + (size_t)row0 * Nout + col)       = pack_f16x2(v0, v1);
                *(uint32_t*)(g_h16 + (size_t)(row0 + 8) * Nout + col) = pack_f16x2(v2, v3);
            }
        }
    }
}

// ---------------- tensor-core ragged flash attention -------------------------
// 128 threads (4 warps), grid (BG, NH, 16 q-tiles of 32).
__global__ __launch_bounds__(128) void attn_kernel()
{
    int b  = blockIdx.x;
    int h  = blockIdx.y;
    int qt = blockIdx.z;
    int cnt = g_counts[b];
    int q0  = qt * 32;
    if (q0 >= cnt) return;
    int start = g_starts[b];
    int nq = min(32, cnt - q0);

    __shared__ __half Qs[32][72];
    __shared__ __half Ks[32][72];
    __shared__ __half Vs[64][40];
    __shared__ __half Ps[32][40];
    __shared__ float  Sc[32][34];
    __shared__ float  s_m[32], s_l[32], s_corr[32];

    const int tid  = threadIdx.x;
    const int warp = tid >> 5;
    const int lane = tid & 31;
    const int grp = lane >> 3, l8 = lane & 7;
    const int rsel = (grp & 1) * 8;
    const int ksel16 = (grp >> 1) * 16;
    const int qr = lane >> 2;
    const int qc = lane & 3;

    const uint32_t qb = smem_u32(&Qs[0][0]);
    const uint32_t kb = smem_u32(&Ks[0][0]);
    const uint32_t vb = smem_u32(&Vs[0][0]);
    const uint32_t pb = smem_u32(&Ps[0][0]);

    {
        const __half* Qg = g_qkv16 + (size_t)(start + q0) * (3 * DM) + h * HD;
        #pragma unroll
        for (int c = tid; c < 256; c += 128) {
            int r = c >> 3, off = (c & 7) * 8;
            uint4 v = make_uint4(0, 0, 0, 0);
            if (r < nq) v = *(const uint4*)(Qg + (size_t)r * (3 * DM) + off);
            *(uint4*)(&Qs[r][off]) = v;
        }
    }
    if (tid < 32) { s_m[tid] = -INFINITY; s_l[tid] = 0.f; }

    float accO[2][2][4];
    #pragma unroll
    for (int i = 0; i < 2; i++)
        #pragma unroll
        for (int j = 0; j < 2; j++)
            #pragma unroll
            for (int r = 0; r < 4; r++) accO[i][j][r] = 0.f;

    const int mi = warp >> 1;
    const int nj = warp & 1;
    const float scale = 0.125f;

    int ktiles = (cnt + 31) >> 5;
    for (int kt = 0; kt < ktiles; kt++) {
        int k0 = kt * 32;
        int nk = min(32, cnt - k0);
        __syncthreads();

        const __half* Kg = g_qkv16 + (size_t)(start + k0) * (3 * DM) + DM + h * HD;
        #pragma unroll
        for (int c = tid; c < 256; c += 128) {
            int r = c >> 3, off = (c & 7) * 8;
            if (r < nk)
                *(uint4*)(&Ks[r][off]) = *(const uint4*)(Kg + (size_t)r * (3 * DM) + off);
        }
        {
            const __half* Vg = g_qkv16 + (size_t)(start + k0) * (3 * DM) + 2 * DM + h * HD;
            int r = lane, dc = warp * 16;
            if (r < nk) {
                const __half* src = Vg + (size_t)r * (3 * DM) + dc;
                #pragma unroll
                for (int i = 0; i < 16; i++) Vs[dc + i][r] = src[i];
            } else {
                #pragma unroll
                for (int i = 0; i < 16; i++) Vs[dc + i][r] = __ushort_as_half(0);
            }
        }
        __syncthreads();

        float accS[2][4] = {{0.f, 0.f, 0.f, 0.f}, {0.f, 0.f, 0.f, 0.f}};
        #pragma unroll
        for (int kc = 0; kc < 4; kc++) {
            uint32_t a0, a1, a2, a3, b0, b1, b2, b3;
            LDMX4(a0, a1, a2, a3,
                  qb + (mi * 16 + rsel + l8) * 144 + kc * 32 + ksel16);
            LDMX4(b0, b1, b2, b3,
                  kb + (nj * 16 + rsel + l8) * 144 + kc * 32 + ksel16);
            uint32_t af[4] = {a0, a1, a2, a3};
            mma_f16(accS[0], af, b0, b2);
            mma_f16(accS[1], af, b1, b3);
        }
        {
            int r0 = mi * 16 + qr;
            #pragma unroll
            for (int jn = 0; jn < 2; jn++) {
                int c0 = nj * 16 + jn * 8 + 2 * qc;
                Sc[r0][c0]         = accS[jn][0] * scale;
                Sc[r0][c0 + 1]     = accS[jn][1] * scale;
                Sc[r0 + 8][c0]     = accS[jn][2] * scale;
                Sc[r0 + 8][c0 + 1] = accS[jn][3] * scale;
            }
        }
        __syncthreads();

        {
            int q = tid >> 2, s4 = tid & 3;
            float v[8];
            float mx = -INFINITY;
            #pragma unroll
            for (int i = 0; i < 8; i++) {
                int k = s4 * 8 + i;
                v[i] = (k < nk) ? Sc[q][k] : -INFINITY;
                mx = fmaxf(mx, v[i]);
            }
            mx = fmaxf(mx, __shfl_xor_sync(0xffffffffu, mx, 1));
            mx = fmaxf(mx, __shfl_xor_sync(0xffffffffu, mx, 2));
            float mold = s_m[q];
            float mnew = fmaxf(mold, mx);
            float sum = 0.f;
            float p[8];
            #pragma unroll
            for (int i = 0; i < 8; i++) {
                p[i] = __expf(v[i] - mnew);
                sum += p[i];
            }
            sum += __shfl_xor_sync(0xffffffffu, sum, 1);
            sum += __shfl_xor_sync(0xffffffffu, sum, 2);
            #pragma unroll
            for (int i = 0; i < 4; i++)
                *(uint32_t*)(&Ps[q][s4 * 8 + 2 * i]) = pack_f16x2(p[2 * i], p[2 * i + 1]);
            if (s4 == 0) {
                float corr = __expf(mold - mnew);
                s_m[q] = mnew;
                s_l[q] = s_l[q] * corr + sum;
                s_corr[q] = corr;
            }
        }
        __syncthreads();

        {
            #pragma unroll
            for (int m2 = 0; m2 < 2; m2++) {
                float c0 = s_corr[m2 * 16 + qr];
                float c1 = s_corr[m2 * 16 + qr + 8];
                #pragma unroll
                for (int jn = 0; jn < 2; jn++) {
                    accO[m2][jn][0] *= c0; accO[m2][jn][1] *= c0;
                    accO[m2][jn][2] *= c1; accO[m2][jn][3] *= c1;
                }
            }
            #pragma unroll
            for (int kc = 0; kc < 2; kc++) {
                uint32_t b0, b1, b2, b3;
                LDMX4(b0, b1, b2, b3,
                      vb + (warp * 16 + rsel + l8) * 80 + kc * 32 + ksel16);
                #pragma unroll
                for (int m2 = 0; m2 < 2; m2++) {
                    uint32_t a0, a1, a2, a3;
                    LDMX4(a0, a1, a2, a3,
                          pb + (m2 * 16 + rsel + l8) * 80 + kc * 32 + ksel16);
                    uint32_t af[4] = {a0, a1, a2, a3};
                    mma_f16(accO[m2][0], af, b0, b2);
                    mma_f16(accO[m2][1], af, b1, b3);
                }
            }
        }
    }

    #pragma unroll
    for (int m2 = 0; m2 < 2; m2++) {
        int r = m2 * 16 + qr;
        int r2 = r + 8;
        float inv  = (r  < nq) ? 1.f / s_l[r]  : 0.f;
        float inv2 = (r2 < nq) ? 1.f / s_l[r2] : 0.f;
        #pragma unroll
        for (int jn = 0; jn < 2; jn++) {
            int col = h * HD + warp * 16 + jn * 8 + 2 * qc;
            if (r < nq)
                *(uint32_t*)(g_t16 + (size_t)(start + q0 + r) * DM + col) =
                    pack_f16x2(accO[m2][jn][0] * inv, accO[m2][jn][1] * inv);
            if (r2 < nq)
                *(uint32_t*)(g_t16 + (size_t)(start + q0 + r2) * DM + col) =
                    pack_f16x2(accO[m2][jn][2] * inv2, accO[m2][jn][3] * inv2);
        }
    }
}

// ---------------- residual + layernorm (f32 out + f16 out) -------------------
__global__ __launch_bounds__(128) void ln_kernel(
    int rid, int did, int oid, int oid16,
    const float* __restrict__ gg, const float* __restrict__ bb)
{
    const float* resid = buf_ptr(rid);
    const float* delta = buf_ptr(did);
    float*       out   = buf_ptr(oid);
    __half*      out16 = f16_ptr(oid16);

    int row = blockIdx.x;
    int tid = threadIdx.x;
    size_t base = (size_t)row * DM;

    float v[4];
    float s = 0.f, sq = 0.f;
    #pragma unroll
    for (int i = 0; i < 4; i++) {
        int c = tid + i * 128;
        float x = resid[base + c] + delta[base + c];
        v[i] = x;
        s += x; sq += x * x;
    }
    __shared__ float shs[4], shq[4];
    #pragma unroll
    for (int o = 16; o > 0; o >>= 1) {
        s  += __shfl_down_sync(0xffffffffu, s, o);
        sq += __shfl_down_sync(0xffffffffu, sq, o);
    }
    int w = tid >> 5;
    if ((tid & 31) == 0) { shs[w] = s; shq[w] = sq; }
    __syncthreads();
    float ts = shs[0] + shs[1] + shs[2] + shs[3];
    float tq = shq[0] + shq[1] + shq[2] + shq[3];
    float mean = ts * (1.f / DM);
    float var  = tq * (1.f / DM) - mean * mean;
    float inv  = rsqrtf(fmaxf(var, 0.f) + LN_EPS);
    #pragma unroll
    for (int i = 0; i < 4; i++) {
        int c = tid + i * 128;
        float r = (v[i] - mean) * inv * gg[c] + bb[c];
        out[base + c] = r;
        out16[base + c] = __float2half(r);
    }
}

// ---------------- segment mean pool -----------------------------------------
__global__ __launch_bounds__(256) void pool_kernel()
{
    int b = blockIdx.x;
    int tid = threadIdx.x;
    int cnt = g_counts[b], st = g_starts[b];
    float a0 = 0.f, a1 = 0.f;
    for (int r = 0; r < cnt; r++) {
        size_t base = (size_t)(st + r) * DM;
        a0 += g_h[base + tid];
        a1 += g_h[base + tid + 256];
    }
    float inv = (cnt > 0) ? 1.f / (float)cnt : 0.f;
    g_pooled[b * DM + tid]       = a0 * inv;
    g_pooled[b * DM + tid + 256] = a1 * inv;
}

// ---------------- head ------------------------------------------------------
__global__ __launch_bounds__(256) void head_kernel(
    const float* __restrict__ w1, const float* __restrict__ b1,
    const float* __restrict__ w2, const float* __restrict__ b2,
    float* __restrict__ out)
{
    int b = blockIdx.x;
    int tid = threadIdx.x;
    __shared__ float ps[DM];
    ps[tid]       = g_pooled[b * DM + tid];
    ps[tid + 256] = g_pooled[b * DM + tid + 256];
    __syncthreads();

    int warp = tid >> 5, lane = tid & 31;
    float partial = 0.f;
    for (int j = warp; j < DM; j += 8) {
        float a = 0.f;
        const float* wr = w1 + (size_t)j * DM;
        for (int k = lane; k < DM; k += 32) a = fmaf(ps[k], wr[k], a);
        #pragma unroll
        for (int o = 16; o > 0; o >>= 1) a += __shfl_down_sync(0xffffffffu, a, o);
        if (lane == 0) {
            a += b1[j];
            float sil = a / (1.f + __expf(-a));
            partial = fmaf(sil, w2[j], partial);
        }
    }
    __shared__ float red[8];
    if (lane == 0) red[warp] = partial;
    __syncthreads();
    if (tid == 0) {
        float t = 0.f;
        #pragma unroll
        for (int i = 0; i < 8; i++) t += red[i];
        out[b] = t + b2[0];
    }
}

// ---------------- launch -----------------------------------------------------
extern "C" void kernel_launch(void* const* d_in, const int* in_sizes, int n_in,
                              void* d_out, int out_size)
{
    const float* node_features = (const float*)d_in[0];
    const int*   batch32       = (const int*)d_in[3];
    const float* emb_w    = (const float*)d_in[4];
    const float* emb_b    = (const float*)d_in[5];
    const float* in_proj_w = (const float*)d_in[6];
    const float* in_proj_b = (const float*)d_in[7];
    const float* out_w    = (const float*)d_in[8];
    const float* out_b    = (const float*)d_in[9];
    const float* ln1_g    = (const float*)d_in[10];
    const float* ln1_b    = (const float*)d_in[11];
    const float* ffn_w1   = (const float*)d_in[12];
    const float* ffn_b1   = (const float*)d_in[13];
    const float* ffn_w2   = (const float*)d_in[14];
    const float* ffn_b2   = (const float*)d_in[15];
    const float* ln2_g    = (const float*)d_in[16];
    const float* ln2_b    = (const float*)d_in[17];
    const float* head_w1  = (const float*)d_in[18];
    const float* head_b1  = (const float*)d_in[19];
    const float* head_w2  = (const float*)d_in[20];
    const float* head_b2  = (const float*)d_in[21];
    float* out = (float*)d_out;

    cudaFuncSetAttribute(gemm_tc, cudaFuncAttributeMaxDynamicSharedMemorySize,
                         GEMM_SMEM);

    k_bookkeep<<<1, 256>>>(batch32);
    k_wconvert<<<2048, 256>>>(in_proj_w, out_w, ffn_w1, ffn_w2,
                              node_features, emb_w);

    // embedding: nf16 @ embw^T (K=96 padded) -> g_h + g_h16
    gemm_tc<<<dim3(DM / 128, NN / 128), 128, GEMM_SMEM>>>(
        F16_NF, EMBW_OFF, emb_b, BUF_H, 2, 0, NN, DINP, DM);

    for (int l = 0; l < NL; l++) {
        const float* ipb = in_proj_b + (size_t)l * 3 * DM;
        const float* ob  = out_b + (size_t)l * DM;
        const float* f1b = ffn_b1 + (size_t)l * DFF;
        const float* f2b = ffn_b2 + (size_t)l * DM;

        // qkv = h16 @ ipw^T -> g_qkv16 (f16)
        gemm_tc<<<dim3(3 * DM / 128, NN / 128), 128, GEMM_SMEM>>>(
            F16_H, IPW_OFF + l * IPW_PER, ipb, F16_QKV, 1, 0, NN, DM, 3 * DM);

        // tensor-core attention -> g_t16
        attn_kernel<<<dim3(BG, NH, 16), 128>>>();

        // o proj = t16 @ ow^T -> g_x (f32)
        gemm_tc<<<dim3(DM / 128, NN / 128), 128, GEMM_SMEM>>>(
            F16_T, OW_OFF + l * OW_PER, ob, BUF_X, 0, 0, NN, DM, DM);

        // x = LN(h + o) -> g_x (f32) + g_x16
        ln_kernel<<<NN, 128>>>(BUF_H, BUF_X, BUF_X, F16_X,
                               ln1_g + (size_t)l * DM, ln1_b + (size_t)l * DM);

        // ffn1 = relu(x16 @ f1w^T) -> g_f16 (f16)
        gemm_tc<<<dim3(DFF / 128, NN / 128), 128, GEMM_SMEM>>>(
            F16_X, F1W_OFF + l * F1W_PER, f1b, F16_F, 1, 1, NN, DM, DFF);

        // ffn2 = f16 @ f2w^T -> g_qkv (f32 scratch)
        gemm_tc<<<dim3(DM / 128, NN / 128), 128, GEMM_SMEM>>>(
            F16_F, F2W_OFF + l * F2W_PER, f2b, BUF_QKV, 0, 0, NN, DFF, DM);

        // h = LN(x + ffn2) -> g_h (f32) + g_h16
        ln_kernel<<<NN, 128>>>(BUF_X, BUF_QKV, BUF_H, F16_H,
                               ln2_g + (size_t)l * DM, ln2_b + (size_t)l * DM);
    }

    pool_kernel<<<BG, 256>>>();
    head_kernel<<<BG, 256>>>(head_w1, head_b1, head_w2, head_b2, out);
}